// round 1
// baseline (speedup 1.0000x reference)
#include <cuda_runtime.h>
#include <cuda_bf16.h>
#include <math.h>

// Problem constants
#define LQ   512
#define LK   4096
#define BB   4
#define DD   512
#define DFF  2048
#define HH   8
#define HD   64
#define LN_EPS 1e-5f

// ------------------------- scratch (device globals; no allocs allowed) ----
__device__ float g_t  [LQ * BB * DD];   // LN1(tgt)
__device__ float g_m  [LK * BB * DD];   // LN2(memory)
__device__ float g_q  [LQ * BB * DD];
__device__ float g_k  [LK * BB * DD];
__device__ float g_v  [LK * BB * DD];
__device__ float g_ctx[LQ * BB * DD];
__device__ float g_x1 [LQ * BB * DD];   // residual sums
__device__ float g_xn [LQ * BB * DD];   // LN3 output
__device__ float g_ff1[LQ * BB * DFF];  // relu(xn @ W1^T + b1)

// ------------------------- reductions ------------------------------------
__device__ __forceinline__ float warpReduceSum(float v) {
    #pragma unroll
    for (int o = 16; o > 0; o >>= 1) v += __shfl_down_sync(0xffffffffu, v, o);
    return v;
}
__device__ __forceinline__ float warpReduceMax(float v) {
    #pragma unroll
    for (int o = 16; o > 0; o >>= 1) v = fmaxf(v, __shfl_down_sync(0xffffffffu, v, o));
    return v;
}

// block of 256 threads
__device__ __forceinline__ float blockReduceSum256(float v, float* shared) {
    __syncthreads();                     // protect shared reuse
    int lane = threadIdx.x & 31, wid = threadIdx.x >> 5;
    v = warpReduceSum(v);
    if (lane == 0) shared[wid] = v;
    __syncthreads();
    if (wid == 0) {
        float x = (lane < 8) ? shared[lane] : 0.f;
        #pragma unroll
        for (int o = 4; o > 0; o >>= 1) x += __shfl_down_sync(0xffffffffu, x, o);
        if (lane == 0) shared[0] = x;
    }
    __syncthreads();
    return shared[0];
}

// ------------------------- LayerNorm (row length 512) ---------------------
__global__ void ln_kernel(const float* __restrict__ in,
                          const float* __restrict__ w,
                          const float* __restrict__ b,
                          float* __restrict__ out)
{
    __shared__ float red[8];
    const int r = blockIdx.x;
    const float* xp = in + (size_t)r * DD;
    float* op = out + (size_t)r * DD;
    int t = threadIdx.x;

    float x0 = xp[t], x1 = xp[t + 256];
    float s = blockReduceSum256(x0 + x1, red);
    float mu = s * (1.0f / DD);
    float d0 = x0 - mu, d1 = x1 - mu;
    float ss = blockReduceSum256(d0 * d0 + d1 * d1, red);
    float var = ss * (1.0f / DD);
    float rstd = rsqrtf(var + LN_EPS);
    op[t]       = d0 * rstd * w[t]       + b[t];
    op[t + 256] = d1 * rstd * w[t + 256] + b[t + 256];
}

// ------------------------- GEMM: out[R,N] = A[R,K] @ W[N,K]^T + bias ------
// optional relu, optional residual add. 64x64x16 tiles, 256 threads, 4x4.
#define BM 64
#define BN 64
#define BK 16
__global__ void gemm_bias_kernel(const float* __restrict__ A,
                                 const float* __restrict__ W,
                                 const float* __restrict__ bias,
                                 const float* __restrict__ res,
                                 float* __restrict__ out,
                                 int R, int N, int K, int doRelu)
{
    __shared__ float As[BK][BM];
    __shared__ float Bs[BK][BN];

    int tid = threadIdx.x;
    int tx = tid & 15;          // N dir
    int ty = tid >> 4;          // M dir
    int rowBase = blockIdx.y * BM;
    int colBase = blockIdx.x * BN;

    int lr = tid >> 2;          // 0..63
    int lc = (tid & 3) * 4;     // 0,4,8,12
    const float* Ag = A + (size_t)(rowBase + lr) * K + lc;
    const float* Wg = W + (size_t)(colBase + lr) * K + lc;

    float acc[4][4];
    #pragma unroll
    for (int i = 0; i < 4; i++)
        #pragma unroll
        for (int j = 0; j < 4; j++) acc[i][j] = 0.f;

    for (int k0 = 0; k0 < K; k0 += BK) {
        float4 av = *(const float4*)(Ag + k0);
        float4 wv = *(const float4*)(Wg + k0);
        As[lc + 0][lr] = av.x; As[lc + 1][lr] = av.y;
        As[lc + 2][lr] = av.z; As[lc + 3][lr] = av.w;
        Bs[lc + 0][lr] = wv.x; Bs[lc + 1][lr] = wv.y;
        Bs[lc + 2][lr] = wv.z; Bs[lc + 3][lr] = wv.w;
        __syncthreads();
        #pragma unroll
        for (int kk = 0; kk < BK; kk++) {
            float a[4], b[4];
            #pragma unroll
            for (int i = 0; i < 4; i++) a[i] = As[kk][ty * 4 + i];
            #pragma unroll
            for (int j = 0; j < 4; j++) b[j] = Bs[kk][tx * 4 + j];
            #pragma unroll
            for (int i = 0; i < 4; i++)
                #pragma unroll
                for (int j = 0; j < 4; j++) acc[i][j] += a[i] * b[j];
        }
        __syncthreads();
    }

    #pragma unroll
    for (int i = 0; i < 4; i++) {
        int row = rowBase + ty * 4 + i;
        #pragma unroll
        for (int j = 0; j < 4; j++) {
            int col = colBase + tx * 4 + j;
            float v = acc[i][j] + bias[col];
            if (doRelu) v = fmaxf(v, 0.f);
            if (res) v += res[(size_t)row * N + col];
            out[(size_t)row * N + col] = v;
        }
    }
}

// ------------------------- fused banded attention -------------------------
// grid (LQ, BB), 256 threads. Handles 1 query row, all 8 heads.
// Allowed band: qi<409 -> [qi*8, qi*8+827); qi>=409 -> [3268, 4096).
#define SW 832   // padded band width
__global__ void attn_kernel(const float* __restrict__ q,
                            const float* __restrict__ k,
                            const float* __restrict__ v,
                            float* __restrict__ ctx,
                            float* __restrict__ aw)
{
    __shared__ float sQ[DD];
    __shared__ float sS[HH][SW];
    __shared__ float sInv[HH];

    const int qi = blockIdx.x;
    const int b  = blockIdx.y;
    const int tid = threadIdx.x;

    int start, end;
    if (qi >= 409) { start = 3268; end = 4096; }
    else           { start = qi * 8; end = start + 827; }
    const int Wd = end - start;

    // load q row into smem
    for (int i = tid; i < DD; i += 256)
        sQ[i] = q[((size_t)qi * BB + b) * DD + i];
    __syncthreads();

    const float scale = 0.125f;  // 1/sqrt(64)

    // scores over the band, all heads
    for (int idx = tid; idx < Wd; idx += 256) {
        const float4* kp = (const float4*)(k + ((size_t)(start + idx) * BB + b) * DD);
        const float4* qp = (const float4*)sQ;
        #pragma unroll
        for (int h = 0; h < HH; h++) {
            float s = 0.f;
            #pragma unroll
            for (int c = 0; c < 16; c++) {
                float4 kv = kp[h * 16 + c];
                float4 qv = qp[h * 16 + c];
                s += kv.x * qv.x + kv.y * qv.y + kv.z * qv.z + kv.w * qv.w;
            }
            sS[h][idx] = s * scale;
        }
    }
    __syncthreads();

    // per-head softmax: warp w owns head w (256 threads = 8 warps)
    {
        int h = tid >> 5, lane = tid & 31;
        float m = -1e30f;
        for (int idx = lane; idx < Wd; idx += 32) m = fmaxf(m, sS[h][idx]);
        m = warpReduceMax(m);
        m = __shfl_sync(0xffffffffu, m, 0);
        float sum = 0.f;
        for (int idx = lane; idx < Wd; idx += 32) {
            float e = __expf(sS[h][idx] - m);
            sS[h][idx] = e;
            sum += e;
        }
        sum = warpReduceSum(sum);
        if (lane == 0) sInv[h] = 1.0f / sum;
    }
    __syncthreads();

    // attn_weights: mean over heads; zeros outside band
    {
        float inv[HH];
        #pragma unroll
        for (int h = 0; h < HH; h++) inv[h] = sInv[h];
        const size_t awBase = ((size_t)b * LQ + qi) * LK;
        for (int j = tid; j < LK; j += 256) {
            float val = 0.f;
            if (j >= start && j < end) {
                int idx = j - start;
                float t = 0.f;
                #pragma unroll
                for (int h = 0; h < HH; h++) t += sS[h][idx] * inv[h];
                val = t * 0.125f;   // 1/H
            }
            aw[awBase + j] = val;
        }
    }

    // context: ctx[qi,b,o] = sum_idx p[h][idx] * v[start+idx,b,o], h = o/64
    for (int o = tid; o < DD; o += 256) {
        int h = o >> 6;
        const float* vp = v + ((size_t)start * BB + b) * DD + o;
        float acc = 0.f;
        for (int idx = 0; idx < Wd; idx++)
            acc += sS[h][idx] * vp[(size_t)idx * BB * DD];
        ctx[((size_t)qi * BB + b) * DD + o] = acc * sInv[h];
    }
}

// ------------------------- launch -----------------------------------------
extern "C" void kernel_launch(void* const* d_in, const int* in_sizes, int n_in,
                              void* d_out, int out_size)
{
    const float* tgt    = (const float*)d_in[0];
    const float* memory = (const float*)d_in[1];
    const float* Wq = (const float*)d_in[2];  const float* bq = (const float*)d_in[3];
    const float* Wk = (const float*)d_in[4];  const float* bk = (const float*)d_in[5];
    const float* Wv = (const float*)d_in[6];  const float* bv = (const float*)d_in[7];
    const float* Wo = (const float*)d_in[8];  const float* bo = (const float*)d_in[9];
    const float* W1 = (const float*)d_in[10]; const float* b1 = (const float*)d_in[11];
    const float* W2 = (const float*)d_in[12]; const float* b2 = (const float*)d_in[13];
    const float* ln1w = (const float*)d_in[14]; const float* ln1b = (const float*)d_in[15];
    const float* ln2w = (const float*)d_in[16]; const float* ln2b = (const float*)d_in[17];
    const float* ln3w = (const float*)d_in[18]; const float* ln3b = (const float*)d_in[19];
    const float* ln4w = (const float*)d_in[20]; const float* ln4b = (const float*)d_in[21];

    float* out    = (float*)d_out;
    float* out_x  = out;                          // [LQ,BB,DD]
    float* out_aw = out + (size_t)LQ * BB * DD;   // [BB,LQ,LK]

    float *t_, *m_, *q_, *k_, *v_, *ctx_, *x1_, *xn_, *ff1_;
    cudaGetSymbolAddress((void**)&t_,  g_t);
    cudaGetSymbolAddress((void**)&m_,  g_m);
    cudaGetSymbolAddress((void**)&q_,  g_q);
    cudaGetSymbolAddress((void**)&k_,  g_k);
    cudaGetSymbolAddress((void**)&v_,  g_v);
    cudaGetSymbolAddress((void**)&ctx_,g_ctx);
    cudaGetSymbolAddress((void**)&x1_, g_x1);
    cudaGetSymbolAddress((void**)&xn_, g_xn);
    cudaGetSymbolAddress((void**)&ff1_,g_ff1);

    // LN1 / LN2
    ln_kernel<<<LQ * BB, 256>>>(tgt,    ln1w, ln1b, t_);
    ln_kernel<<<LK * BB, 256>>>(memory, ln2w, ln2b, m_);

    // Q/K/V projections
    gemm_bias_kernel<<<dim3(DD / BN, (LQ * BB) / BM), 256>>>(t_, Wq, bq, nullptr, q_, LQ * BB, DD, DD, 0);
    gemm_bias_kernel<<<dim3(DD / BN, (LK * BB) / BM), 256>>>(m_, Wk, bk, nullptr, k_, LK * BB, DD, DD, 0);
    gemm_bias_kernel<<<dim3(DD / BN, (LK * BB) / BM), 256>>>(m_, Wv, bv, nullptr, v_, LK * BB, DD, DD, 0);

    // fused banded attention (ctx + attn_weights)
    attn_kernel<<<dim3(LQ, BB), 256>>>(q_, k_, v_, ctx_, out_aw);

    // output projection + residual (t), LN3
    gemm_bias_kernel<<<dim3(DD / BN, (LQ * BB) / BM), 256>>>(ctx_, Wo, bo, t_, x1_, LQ * BB, DD, DD, 0);
    ln_kernel<<<LQ * BB, 256>>>(x1_, ln3w, ln3b, xn_);

    // FFN
    gemm_bias_kernel<<<dim3(DFF / BN, (LQ * BB) / BM), 256>>>(xn_, W1, b1, nullptr, ff1_, LQ * BB, DFF, DD, 1);
    gemm_bias_kernel<<<dim3(DD / BN, (LQ * BB) / BM), 256>>>(ff1_, W2, b2, xn_, x1_, LQ * BB, DD, DFF, 0);

    // LN4 -> output x
    ln_kernel<<<LQ * BB, 256>>>(x1_, ln4w, ln4b, out_x);
}

// round 2
// speedup vs baseline: 1.9130x; 1.9130x over previous
#include <cuda_runtime.h>
#include <cuda_bf16.h>
#include <math.h>

// Problem constants
#define LQ   512
#define LK   4096
#define BB   4
#define DD   512
#define DFF  2048
#define HH   8
#define HD   64
#define LN_EPS 1e-5f

// ------------------------- scratch (device globals) -----------------------
__device__ float g_t  [LQ * BB * DD];
__device__ float g_m  [LK * BB * DD];
__device__ float g_q  [LQ * BB * DD];
__device__ float g_k  [LK * BB * DD];
__device__ float g_v  [LK * BB * DD];
__device__ float g_ctx[LQ * BB * DD];
__device__ float g_x1 [LQ * BB * DD];
__device__ float g_xn [LQ * BB * DD];
__device__ float g_ff1[LQ * BB * DFF];

// ------------------------- reductions ------------------------------------
__device__ __forceinline__ float warpReduceSum(float v) {
    #pragma unroll
    for (int o = 16; o > 0; o >>= 1) v += __shfl_down_sync(0xffffffffu, v, o);
    return v;
}
__device__ __forceinline__ float warpReduceMax(float v) {
    #pragma unroll
    for (int o = 16; o > 0; o >>= 1) v = fmaxf(v, __shfl_down_sync(0xffffffffu, v, o));
    return v;
}
__device__ __forceinline__ float blockReduceSum256(float v, float* shared) {
    __syncthreads();
    int lane = threadIdx.x & 31, wid = threadIdx.x >> 5;
    v = warpReduceSum(v);
    if (lane == 0) shared[wid] = v;
    __syncthreads();
    if (wid == 0) {
        float x = (lane < 8) ? shared[lane] : 0.f;
        #pragma unroll
        for (int o = 4; o > 0; o >>= 1) x += __shfl_down_sync(0xffffffffu, x, o);
        if (lane == 0) shared[0] = x;
    }
    __syncthreads();
    return shared[0];
}

// ------------------------- LayerNorm (row length 512) ---------------------
__global__ void ln_kernel(const float* __restrict__ in,
                          const float* __restrict__ w,
                          const float* __restrict__ b,
                          float* __restrict__ out)
{
    __shared__ float red[8];
    const int r = blockIdx.x;
    const float* xp = in + (size_t)r * DD;
    float* op = out + (size_t)r * DD;
    int t = threadIdx.x;

    float x0 = xp[t], x1 = xp[t + 256];
    float s = blockReduceSum256(x0 + x1, red);
    float mu = s * (1.0f / DD);
    float d0 = x0 - mu, d1 = x1 - mu;
    float ss = blockReduceSum256(d0 * d0 + d1 * d1, red);
    float rstd = rsqrtf(ss * (1.0f / DD) + LN_EPS);
    op[t]       = d0 * rstd * w[t]       + b[t];
    op[t + 256] = d1 * rstd * w[t + 256] + b[t + 256];
}

// ------------------------- GEMM: out[R,N] = A[R,K] @ W[N,K]^T + bias ------
// 128x64x16 tiles, 256 threads, 8x4 microtile, double-buffered smem.
#define GBM 128
#define GBN 64
#define GBK 16
#define ASTR (GBM + 4)   // padded strides to cut STS bank conflicts
#define BSTR (GBN + 4)

__global__ __launch_bounds__(256) void gemm_kernel(
        const float* __restrict__ A,
        const float* __restrict__ W,
        const float* __restrict__ bias,
        const float* __restrict__ res,
        float* __restrict__ out,
        int R, int N, int K, int doRelu)
{
    __shared__ float As[2][GBK * ASTR];
    __shared__ float Bs[2][GBK * BSTR];

    const int tid = threadIdx.x;
    const int tx = tid & 15;        // N dir (4 cols)
    const int ty = tid >> 4;        // M dir (8 rows)
    const int rowBase = blockIdx.y * GBM;
    const int colBase = blockIdx.x * GBN;

    // global-load mapping
    const int lr = tid >> 2;           // 0..63
    const int lc = (tid & 3) * 4;      // 0,4,8,12
    const float* Ag0 = A + (size_t)(rowBase + lr) * K + lc;
    const float* Ag1 = A + (size_t)(rowBase + lr + 64) * K + lc;
    const float* Wg  = W + (size_t)(colBase + lr) * K + lc;

    float acc[8][4];
    #pragma unroll
    for (int i = 0; i < 8; i++)
        #pragma unroll
        for (int j = 0; j < 4; j++) acc[i][j] = 0.f;

    // prologue: tile 0 -> buf 0
    float4 a0 = *(const float4*)(Ag0);
    float4 a1 = *(const float4*)(Ag1);
    float4 w0 = *(const float4*)(Wg);
    {
        float* as = As[0]; float* bs = Bs[0];
        as[(lc+0)*ASTR + lr] = a0.x; as[(lc+1)*ASTR + lr] = a0.y;
        as[(lc+2)*ASTR + lr] = a0.z; as[(lc+3)*ASTR + lr] = a0.w;
        as[(lc+0)*ASTR + lr+64] = a1.x; as[(lc+1)*ASTR + lr+64] = a1.y;
        as[(lc+2)*ASTR + lr+64] = a1.z; as[(lc+3)*ASTR + lr+64] = a1.w;
        bs[(lc+0)*BSTR + lr] = w0.x; bs[(lc+1)*BSTR + lr] = w0.y;
        bs[(lc+2)*BSTR + lr] = w0.z; bs[(lc+3)*BSTR + lr] = w0.w;
    }
    __syncthreads();

    const int numTiles = K / GBK;
    int buf = 0;
    for (int t = 1; t < numTiles; t++) {
        // prefetch next tile to registers
        a0 = *(const float4*)(Ag0 + t * GBK);
        a1 = *(const float4*)(Ag1 + t * GBK);
        w0 = *(const float4*)(Wg  + t * GBK);

        // compute on current buffer
        const float* as = As[buf]; const float* bs = Bs[buf];
        #pragma unroll
        for (int kk = 0; kk < GBK; kk++) {
            float av[8], bv[4];
            *(float4*)(av)     = *(const float4*)(as + kk*ASTR + ty*8);
            *(float4*)(av + 4) = *(const float4*)(as + kk*ASTR + ty*8 + 4);
            *(float4*)(bv)     = *(const float4*)(bs + kk*BSTR + tx*4);
            #pragma unroll
            for (int i = 0; i < 8; i++)
                #pragma unroll
                for (int j = 0; j < 4; j++) acc[i][j] += av[i] * bv[j];
        }

        // store prefetched data into the other buffer
        float* asn = As[buf^1]; float* bsn = Bs[buf^1];
        asn[(lc+0)*ASTR + lr] = a0.x; asn[(lc+1)*ASTR + lr] = a0.y;
        asn[(lc+2)*ASTR + lr] = a0.z; asn[(lc+3)*ASTR + lr] = a0.w;
        asn[(lc+0)*ASTR + lr+64] = a1.x; asn[(lc+1)*ASTR + lr+64] = a1.y;
        asn[(lc+2)*ASTR + lr+64] = a1.z; asn[(lc+3)*ASTR + lr+64] = a1.w;
        bsn[(lc+0)*BSTR + lr] = w0.x; bsn[(lc+1)*BSTR + lr] = w0.y;
        bsn[(lc+2)*BSTR + lr] = w0.z; bsn[(lc+3)*BSTR + lr] = w0.w;
        __syncthreads();
        buf ^= 1;
    }
    // last tile
    {
        const float* as = As[buf]; const float* bs = Bs[buf];
        #pragma unroll
        for (int kk = 0; kk < GBK; kk++) {
            float av[8], bv[4];
            *(float4*)(av)     = *(const float4*)(as + kk*ASTR + ty*8);
            *(float4*)(av + 4) = *(const float4*)(as + kk*ASTR + ty*8 + 4);
            *(float4*)(bv)     = *(const float4*)(bs + kk*BSTR + tx*4);
            #pragma unroll
            for (int i = 0; i < 8; i++)
                #pragma unroll
                for (int j = 0; j < 4; j++) acc[i][j] += av[i] * bv[j];
        }
    }

    // epilogue
    const int col = colBase + tx * 4;
    float4 bv4 = *(const float4*)(bias + col);
    #pragma unroll
    for (int i = 0; i < 8; i++) {
        int row = rowBase + ty * 8 + i;
        float4 v;
        v.x = acc[i][0] + bv4.x; v.y = acc[i][1] + bv4.y;
        v.z = acc[i][2] + bv4.z; v.w = acc[i][3] + bv4.w;
        if (doRelu) {
            v.x = fmaxf(v.x, 0.f); v.y = fmaxf(v.y, 0.f);
            v.z = fmaxf(v.z, 0.f); v.w = fmaxf(v.w, 0.f);
        }
        if (res) {
            float4 rv = *(const float4*)(res + (size_t)row * N + col);
            v.x += rv.x; v.y += rv.y; v.z += rv.z; v.w += rv.w;
        }
        *(float4*)(out + (size_t)row * N + col) = v;
    }
}

// ------------------------- fused banded attention -------------------------
// QT query rows per block, all 8 heads. 256 threads, dynamic smem.
#define QT 4
#define SW 832   // padded per-row band width (max 828)
#define SMEM_ATTN ((QT*DD + QT*HH*SW + QT*HH) * 4)

__global__ __launch_bounds__(256) void attn_kernel(
        const float* __restrict__ q,
        const float* __restrict__ k,
        const float* __restrict__ v,
        float* __restrict__ ctx,
        float* __restrict__ aw)
{
    extern __shared__ float smem[];
    float* sQ   = smem;                    // QT*DD
    float* sS   = smem + QT * DD;          // QT*HH*SW
    float* sInv = sS + QT * HH * SW;       // QT*HH

    const int qi0 = blockIdx.x * QT;
    const int b   = blockIdx.y;
    const int tid = threadIdx.x;

    int start[QT], wd[QT];
    #pragma unroll
    for (int r = 0; r < QT; r++) {
        int qi = qi0 + r;
        if (qi >= 409) { start[r] = 3268; wd[r] = 828; }
        else           { start[r] = qi * 8; wd[r] = 827; }
    }
    const int ustart = start[0];
    const int uend   = start[QT-1] + wd[QT-1];
    const int uW     = uend - ustart;

    // load QT q rows into smem
    for (int i = tid; i < QT * DD; i += 256) {
        int r = i / DD, c = i % DD;
        sQ[i] = q[((size_t)(qi0 + r) * BB + b) * DD + c];
    }
    __syncthreads();

    const float scale = 0.125f;  // 1/sqrt(64)

    // scores: each thread handles one union-band key index at a time
    for (int idx = tid; idx < uW; idx += 256) {
        const int gk = ustart + idx;
        const float4* kp = (const float4*)(k + ((size_t)gk * BB + b) * DD);
        int jj[QT]; bool in[QT];
        #pragma unroll
        for (int r = 0; r < QT; r++) {
            jj[r] = gk - start[r];
            in[r] = (jj[r] >= 0) && (jj[r] < wd[r]);
        }
        #pragma unroll
        for (int h = 0; h < HH; h++) {
            float acc[QT];
            #pragma unroll
            for (int r = 0; r < QT; r++) acc[r] = 0.f;
            #pragma unroll
            for (int c = 0; c < 16; c++) {
                float4 kv = kp[h * 16 + c];
                #pragma unroll
                for (int r = 0; r < QT; r++) {
                    float4 qv = ((const float4*)(sQ + r * DD))[h * 16 + c];
                    acc[r] += kv.x*qv.x + kv.y*qv.y + kv.z*qv.z + kv.w*qv.w;
                }
            }
            #pragma unroll
            for (int r = 0; r < QT; r++)
                if (in[r]) sS[(r * HH + h) * SW + jj[r]] = acc[r] * scale;
        }
    }
    __syncthreads();

    // softmax: warp per (r,h) pair, 32 pairs over 8 warps
    {
        const int wid = tid >> 5, lane = tid & 31;
        for (int p = wid; p < QT * HH; p += 8) {
            const int r = p >> 3;
            float* s = sS + p * SW;
            const int W = wd[r];
            float m = -1e30f;
            for (int i = lane; i < W; i += 32) m = fmaxf(m, s[i]);
            m = warpReduceMax(m);
            m = __shfl_sync(0xffffffffu, m, 0);
            float sum = 0.f;
            for (int i = lane; i < W; i += 32) {
                float e = __expf(s[i] - m);
                s[i] = e;
                sum += e;
            }
            sum = warpReduceSum(sum);
            if (lane == 0) sInv[p] = 1.0f / sum;
        }
    }
    __syncthreads();

    // attn_weights: mean over heads; zeros outside band
    #pragma unroll
    for (int r = 0; r < QT; r++) {
        float inv[HH];
        #pragma unroll
        for (int h = 0; h < HH; h++) inv[h] = sInv[r * HH + h];
        const size_t base = ((size_t)b * LQ + (qi0 + r)) * LK;
        for (int j = tid; j < LK; j += 256) {
            float val = 0.f;
            int idx = j - start[r];
            if (idx >= 0 && idx < wd[r]) {
                float t = 0.f;
                #pragma unroll
                for (int h = 0; h < HH; h++) t += sS[(r * HH + h) * SW + idx] * inv[h];
                val = t * 0.125f;  // 1/H
            }
            aw[base + j] = val;
        }
    }

    // context: each thread owns outputs o=tid and o=tid+256 for all QT rows
    {
        const int o1 = tid, o2 = tid + 256;
        const int h1 = o1 >> 6, h2 = o2 >> 6;
        float acc1[QT], acc2[QT];
        #pragma unroll
        for (int r = 0; r < QT; r++) { acc1[r] = 0.f; acc2[r] = 0.f; }
        const float* vb = v + ((size_t)ustart * BB + b) * DD;

        #pragma unroll 4
        for (int idx = 0; idx < uW; idx++) {
            const float v1 = vb[(size_t)idx * (BB * DD) + o1];
            const float v2 = vb[(size_t)idx * (BB * DD) + o2];
            const int gk = ustart + idx;
            #pragma unroll
            for (int r = 0; r < QT; r++) {
                int j = gk - start[r];
                if (j >= 0 && j < wd[r]) {
                    acc1[r] += sS[(r * HH + h1) * SW + j] * v1;
                    acc2[r] += sS[(r * HH + h2) * SW + j] * v2;
                }
            }
        }
        #pragma unroll
        for (int r = 0; r < QT; r++) {
            ctx[((size_t)(qi0 + r) * BB + b) * DD + o1] = acc1[r] * sInv[r * HH + h1];
            ctx[((size_t)(qi0 + r) * BB + b) * DD + o2] = acc2[r] * sInv[r * HH + h2];
        }
    }
}

// ------------------------- launch -----------------------------------------
extern "C" void kernel_launch(void* const* d_in, const int* in_sizes, int n_in,
                              void* d_out, int out_size)
{
    const float* tgt    = (const float*)d_in[0];
    const float* memory = (const float*)d_in[1];
    const float* Wq = (const float*)d_in[2];  const float* bq = (const float*)d_in[3];
    const float* Wk = (const float*)d_in[4];  const float* bk = (const float*)d_in[5];
    const float* Wv = (const float*)d_in[6];  const float* bv = (const float*)d_in[7];
    const float* Wo = (const float*)d_in[8];  const float* bo = (const float*)d_in[9];
    const float* W1 = (const float*)d_in[10]; const float* b1 = (const float*)d_in[11];
    const float* W2 = (const float*)d_in[12]; const float* b2 = (const float*)d_in[13];
    const float* ln1w = (const float*)d_in[14]; const float* ln1b = (const float*)d_in[15];
    const float* ln2w = (const float*)d_in[16]; const float* ln2b = (const float*)d_in[17];
    const float* ln3w = (const float*)d_in[18]; const float* ln3b = (const float*)d_in[19];
    const float* ln4w = (const float*)d_in[20]; const float* ln4b = (const float*)d_in[21];

    float* out    = (float*)d_out;
    float* out_x  = out;
    float* out_aw = out + (size_t)LQ * BB * DD;

    float *t_, *m_, *q_, *k_, *v_, *ctx_, *x1_, *xn_, *ff1_;
    cudaGetSymbolAddress((void**)&t_,  g_t);
    cudaGetSymbolAddress((void**)&m_,  g_m);
    cudaGetSymbolAddress((void**)&q_,  g_q);
    cudaGetSymbolAddress((void**)&k_,  g_k);
    cudaGetSymbolAddress((void**)&v_,  g_v);
    cudaGetSymbolAddress((void**)&ctx_,g_ctx);
    cudaGetSymbolAddress((void**)&x1_, g_x1);
    cudaGetSymbolAddress((void**)&xn_, g_xn);
    cudaGetSymbolAddress((void**)&ff1_,g_ff1);

    cudaFuncSetAttribute(attn_kernel, cudaFuncAttributeMaxDynamicSharedMemorySize, SMEM_ATTN);

    // LN1 / LN2
    ln_kernel<<<LQ * BB, 256>>>(tgt,    ln1w, ln1b, t_);
    ln_kernel<<<LK * BB, 256>>>(memory, ln2w, ln2b, m_);

    // Q/K/V projections
    gemm_kernel<<<dim3(DD / GBN, (LQ * BB) / GBM), 256>>>(t_, Wq, bq, nullptr, q_, LQ * BB, DD, DD, 0);
    gemm_kernel<<<dim3(DD / GBN, (LK * BB) / GBM), 256>>>(m_, Wk, bk, nullptr, k_, LK * BB, DD, DD, 0);
    gemm_kernel<<<dim3(DD / GBN, (LK * BB) / GBM), 256>>>(m_, Wv, bv, nullptr, v_, LK * BB, DD, DD, 0);

    // fused banded attention
    attn_kernel<<<dim3(LQ / QT, BB), 256, SMEM_ATTN>>>(q_, k_, v_, ctx_, out_aw);

    // output projection + residual, LN3
    gemm_kernel<<<dim3(DD / GBN, (LQ * BB) / GBM), 256>>>(ctx_, Wo, bo, t_, x1_, LQ * BB, DD, DD, 0);
    ln_kernel<<<LQ * BB, 256>>>(x1_, ln3w, ln3b, xn_);

    // FFN
    gemm_kernel<<<dim3(DFF / GBN, (LQ * BB) / GBM), 256>>>(xn_, W1, b1, nullptr, ff1_, LQ * BB, DFF, DD, 1);
    gemm_kernel<<<dim3(DD / GBN, (LQ * BB) / GBM), 256>>>(ff1_, W2, b2, xn_, x1_, LQ * BB, DD, DFF, 0);

    // LN4 -> output x
    ln_kernel<<<LQ * BB, 256>>>(x1_, ln4w, ln4b, out_x);
}